// round 2
// baseline (speedup 1.0000x reference)
#include <cuda_runtime.h>

// Problem constants (fixed by the dataset)
#define C_CH    192
#define HW      4096         // H*W = 64*64 : one block's slab
#define NSLAB   3072         // B*C = 16*192
#define PSTRIDE 48

// Per-channel parameter table (written by prep kernel, read by main kernel)
//  [0..2]   m0 = softplus(matrix_0)
//  [3..5]   b0
//  [6..8]   tf0 = tanh(factor_0)
//  [9..17]  M1 (row-major 3x3)
//  [18..20] b1
//  [21..23] tf1
//  [24..32] M2
//  [33..35] b2
//  [36..38] tf2
//  [39..41] m3
//  [42]     b3
//  [43]     A    = m3.M2.M1.m0   (slope of collapsed affine chain; also U-L gap)
//  [44]     affine flag (1.0 iff all tanh(factor)==0)
//  [45]     beta = chain(0) (intercept of collapsed affine chain)
__device__ float g_par[C_CH * PSTRIDE];

__device__ __forceinline__ float softplus_f(float x) {
    return (x > 20.0f) ? x : log1pf(expf(x));
}

__global__ void prep_kernel(const float* __restrict__ m0p,
                            const float* __restrict__ m1p,
                            const float* __restrict__ m2p,
                            const float* __restrict__ m3p,
                            const float* __restrict__ b0p,
                            const float* __restrict__ b1p,
                            const float* __restrict__ b2p,
                            const float* __restrict__ b3p,
                            const float* __restrict__ f0p,
                            const float* __restrict__ f1p,
                            const float* __restrict__ f2p) {
    int c = blockIdx.x * blockDim.x + threadIdx.x;
    if (c >= C_CH) return;
    float* P = g_par + c * PSTRIDE;

    float sm0[3], sb0[3], tf0[3], SM1[9], sb1[3], tf1[3], SM2[9], sb2[3], tf2[3], sm3[3];
    bool affine = true;
    #pragma unroll
    for (int j = 0; j < 3; j++) {
        sm0[j] = softplus_f(m0p[c * 3 + j]);
        sb0[j] = b0p[c * 3 + j];
        tf0[j] = tanhf(f0p[c * 3 + j]);
        affine = affine && (tf0[j] == 0.0f);
    }
    #pragma unroll
    for (int k = 0; k < 9; k++) {
        SM1[k] = softplus_f(m1p[c * 9 + k]);
        SM2[k] = softplus_f(m2p[c * 9 + k]);
    }
    #pragma unroll
    for (int j = 0; j < 3; j++) {
        sb1[j] = b1p[c * 3 + j];
        tf1[j] = tanhf(f1p[c * 3 + j]);
        affine = affine && (tf1[j] == 0.0f);
        sb2[j] = b2p[c * 3 + j];
        tf2[j] = tanhf(f2p[c * 3 + j]);
        affine = affine && (tf2[j] == 0.0f);
        sm3[j] = softplus_f(m3p[c * 3 + j]);
    }
    float sb3 = b3p[c];

    // Slope A = m3 . M2 . M1 . m0 (valid always; equals d(chain)/dt when affine)
    float d1[3], d2[3];
    #pragma unroll
    for (int i = 0; i < 3; i++)
        d1[i] = SM1[i*3+0]*sm0[0] + SM1[i*3+1]*sm0[1] + SM1[i*3+2]*sm0[2];
    #pragma unroll
    for (int i = 0; i < 3; i++)
        d2[i] = SM2[i*3+0]*d1[0] + SM2[i*3+1]*d1[1] + SM2[i*3+2]*d1[2];
    float A = sm3[0]*d2[0] + sm3[1]*d2[1] + sm3[2]*d2[2];

    // Intercept beta = chain(0) when affine: propagate biases only.
    float h0[3], h1[3], h2[3];
    #pragma unroll
    for (int j = 0; j < 3; j++) h0[j] = sb0[j];
    #pragma unroll
    for (int i = 0; i < 3; i++)
        h1[i] = SM1[i*3+0]*h0[0] + SM1[i*3+1]*h0[1] + SM1[i*3+2]*h0[2] + sb1[i];
    #pragma unroll
    for (int i = 0; i < 3; i++)
        h2[i] = SM2[i*3+0]*h1[0] + SM2[i*3+1]*h1[1] + SM2[i*3+2]*h1[2] + sb2[i];
    float beta = sm3[0]*h2[0] + sm3[1]*h2[1] + sm3[2]*h2[2] + sb3;

    #pragma unroll
    for (int j = 0; j < 3; j++) { P[j] = sm0[j]; P[3+j] = sb0[j]; P[6+j] = tf0[j]; }
    #pragma unroll
    for (int k = 0; k < 9; k++) { P[9+k] = SM1[k]; P[24+k] = SM2[k]; }
    #pragma unroll
    for (int j = 0; j < 3; j++) { P[18+j] = sb1[j]; P[21+j] = tf1[j];
                                  P[33+j] = sb2[j]; P[36+j] = tf2[j];
                                  P[39+j] = sm3[j]; }
    P[42] = sb3;
    P[43] = A;
    P[44] = affine ? 1.0f : 0.0f;
    P[45] = beta;
}

// Fast stable sigmoid: clamp keeps __expf/__fdividef out of their bad ranges.
__device__ __forceinline__ float sigmoid_f(float x) {
    x = fmaxf(x, -87.0f);
    return __fdividef(1.0f, 1.0f + __expf(-x));
}

__global__ __launch_bounds__(256)
void ent_kernel(const float4* __restrict__ x4, float4* __restrict__ o4) {
    const int slab = blockIdx.x;              // = b*C + c
    const int c = slab % C_CH;
    const float* __restrict__ P = g_par + c * PSTRIDE;

    const float A      = P[43];
    const bool  affine = (P[44] != 0.0f);     // block-uniform branch
    const int   base   = slab * (HW / 4);

    if (affine) {
        // L = A*(x-0.5) + beta = A*x + B0 ;  U = L + A
        const float B0 = fmaf(-0.5f, A, P[45]);
        #pragma unroll
        for (int k = 0; k < 4; k++) {
            const int idx = base + threadIdx.x + k * 256;
            float4 v = x4[idx];
            float4 r;
            const float* vp = &v.x;
            float* rp = &r.x;
            #pragma unroll
            for (int e = 0; e < 4; e++) {
                const float L = fmaf(A, vp[e], B0);
                const float U = L + A;
                const float sum = L + U;
                const float s = (sum > 0.0f) ? -1.0f : ((sum < 0.0f) ? 1.0f : 0.0f);
                const float like = fabsf(sigmoid_f(s * U) - sigmoid_f(s * L));
                rp[e] = fmaxf(like, 1e-6f);
            }
            o4[idx] = r;
        }
        return;
    }

    // ---- generic (non-affine) fallback: full layered evaluation ----
    float m0[3], b0[3], tf0[3], M1[9], b1[3], tf1[3], M2[9], b2[3], tf2[3], m3[3];
    #pragma unroll
    for (int j = 0; j < 3; j++) { m0[j] = P[j]; b0[j] = P[3+j]; tf0[j] = P[6+j]; }
    #pragma unroll
    for (int k = 0; k < 9; k++) { M1[k] = P[9+k]; M2[k] = P[24+k]; }
    #pragma unroll
    for (int j = 0; j < 3; j++) { b1[j] = P[18+j]; tf1[j] = P[21+j];
                                  b2[j] = P[33+j]; tf2[j] = P[36+j];
                                  m3[j] = P[39+j]; }
    const float b3 = P[42];

    auto chain = [&](float t) -> float {
        float h[3], g[3];
        #pragma unroll
        for (int j = 0; j < 3; j++) {
            h[j] = fmaf(m0[j], t, b0[j]);
            h[j] = fmaf(tf0[j], tanhf(h[j]), h[j]);
        }
        #pragma unroll
        for (int i = 0; i < 3; i++) {
            g[i] = fmaf(M1[i*3+0], h[0], fmaf(M1[i*3+1], h[1], fmaf(M1[i*3+2], h[2], b1[i])));
            g[i] = fmaf(tf1[i], tanhf(g[i]), g[i]);
        }
        #pragma unroll
        for (int i = 0; i < 3; i++) {
            h[i] = fmaf(M2[i*3+0], g[0], fmaf(M2[i*3+1], g[1], fmaf(M2[i*3+2], g[2], b2[i])));
            h[i] = fmaf(tf2[i], tanhf(h[i]), h[i]);
        }
        return fmaf(m3[0], h[0], fmaf(m3[1], h[1], fmaf(m3[2], h[2], b3)));
    };

    #pragma unroll
    for (int k = 0; k < 4; k++) {
        const int idx = base + threadIdx.x + k * 256;
        float4 v = x4[idx];
        float4 r;
        const float* vp = &v.x;
        float* rp = &r.x;
        #pragma unroll
        for (int e = 0; e < 4; e++) {
            const float L = chain(vp[e] - 0.5f);
            const float U = chain(vp[e] + 0.5f);
            const float sum = L + U;
            const float s = (sum > 0.0f) ? -1.0f : ((sum < 0.0f) ? 1.0f : 0.0f);
            const float like = fabsf(sigmoid_f(s * U) - sigmoid_f(s * L));
            rp[e] = fmaxf(like, 1e-6f);
        }
        o4[idx] = r;
    }
}

extern "C" void kernel_launch(void* const* d_in, const int* in_sizes, int n_in,
                              void* d_out, int out_size) {
    const float* x = (const float*)d_in[0];
    const float *m0, *m1, *m2, *m3, *b0, *b1, *b2, *b3, *f0, *f1, *f2;

    // Disambiguate input ordering by element counts:
    //   matrix_1 / matrix_2 are the only 1728-element tensors.
    // setup_inputs dict order: x, m0,b0,f0, m1,b1,f1, m2,b2,f2, m3,b3  -> in_sizes[4]==1728
    // signature order:         x, m0..m3, b0..b3, f0..f2               -> in_sizes[2]==1728
    if (n_in >= 12 && in_sizes[4] == 1728) {
        m0 = (const float*)d_in[1];  b0 = (const float*)d_in[2];  f0 = (const float*)d_in[3];
        m1 = (const float*)d_in[4];  b1 = (const float*)d_in[5];  f1 = (const float*)d_in[6];
        m2 = (const float*)d_in[7];  b2 = (const float*)d_in[8];  f2 = (const float*)d_in[9];
        m3 = (const float*)d_in[10]; b3 = (const float*)d_in[11];
    } else {
        m0 = (const float*)d_in[1];  m1 = (const float*)d_in[2];
        m2 = (const float*)d_in[3];  m3 = (const float*)d_in[4];
        b0 = (const float*)d_in[5];  b1 = (const float*)d_in[6];
        b2 = (const float*)d_in[7];  b3 = (const float*)d_in[8];
        f0 = (const float*)d_in[9];  f1 = (const float*)d_in[10]; f2 = (const float*)d_in[11];
    }

    prep_kernel<<<1, C_CH>>>(m0, m1, m2, m3, b0, b1, b2, b3, f0, f1, f2);
    ent_kernel<<<NSLAB, 256>>>((const float4*)x, (float4*)d_out);
}

// round 3
// speedup vs baseline: 1.2789x; 1.2789x over previous
#include <cuda_runtime.h>

// Problem constants (fixed by the dataset)
#define C_CH    192
#define HW      4096         // H*W = 64*64 : one block's slab
#define NSLAB   3072         // B*C = 16*192

__device__ __forceinline__ float softplus_fast(float x) {
    return (x > 20.0f) ? x : __logf(1.0f + __expf(x));
}

// One fused kernel: per-block prologue derives the channel's collapsed-affine
// constants (or full tables for the generic fallback), then streams the slab.
__global__ __launch_bounds__(256)
void ent_fused_kernel(const float4* __restrict__ x4, float4* __restrict__ o4,
                      const float* __restrict__ m0p, const float* __restrict__ m1p,
                      const float* __restrict__ m2p, const float* __restrict__ m3p,
                      const float* __restrict__ b0p, const float* __restrict__ b1p,
                      const float* __restrict__ b2p, const float* __restrict__ b3p,
                      const float* __restrict__ f0p, const float* __restrict__ f1p,
                      const float* __restrict__ f2p) {
    // Shared tables
    __shared__ float W[24];    // sm0[0..2], M1[3..11], M2[12..20], sm3[21..23]
    __shared__ float TF[9];    // tanh(factor): tf0[0..2], tf1[3..5], tf2[6..8]
    __shared__ float BI[10];   // b0[0..2], b1[3..5], b2[6..8], b3[9]
    __shared__ float CC[7];    // A, B1(=beta+0.5A), KP, KM, DP, DM, affine

    const int slab = blockIdx.x;          // = b*C + c
    const int c = slab % C_CH;
    const int tid = threadIdx.x;

    // ---- prologue: distributed transcendentals ----
    if (tid < 24) {
        // softplus weights: m0(3), M1(9), M2(9), m3(3)
        float v;
        if (tid < 3)       v = m0p[c * 3 + tid];
        else if (tid < 12) v = m1p[c * 9 + (tid - 3)];
        else if (tid < 21) v = m2p[c * 9 + (tid - 12)];
        else               v = m3p[c * 3 + (tid - 21)];
        W[tid] = softplus_fast(v);
    } else if (tid >= 32 && tid < 41) {
        int j = tid - 32;
        float f = (j < 3) ? f0p[c * 3 + j] : (j < 6) ? f1p[c * 3 + (j - 3)]
                                           : f2p[c * 3 + (j - 6)];
        TF[j] = tanhf(f);
    } else if (tid >= 64 && tid < 74) {
        int j = tid - 64;
        BI[j] = (j < 3) ? b0p[c * 3 + j] : (j < 6) ? b1p[c * 3 + (j - 3)]
              : (j < 9) ? b2p[c * 3 + (j - 6)] : b3p[c];
    }
    __syncthreads();

    if (tid == 0) {
        const float* sm0 = W;
        const float* M1  = W + 3;
        const float* M2  = W + 12;
        const float* sm3 = W + 21;
        // slope A = m3 . M2 . M1 . m0
        float d1[3], d2[3];
        #pragma unroll
        for (int i = 0; i < 3; i++)
            d1[i] = M1[i*3+0]*sm0[0] + M1[i*3+1]*sm0[1] + M1[i*3+2]*sm0[2];
        #pragma unroll
        for (int i = 0; i < 3; i++)
            d2[i] = M2[i*3+0]*d1[0] + M2[i*3+1]*d1[1] + M2[i*3+2]*d1[2];
        float A = sm3[0]*d2[0] + sm3[1]*d2[1] + sm3[2]*d2[2];
        // intercept beta = chain(0): biases only
        float h1[3], h2[3];
        #pragma unroll
        for (int i = 0; i < 3; i++)
            h1[i] = M1[i*3+0]*BI[0] + M1[i*3+1]*BI[1] + M1[i*3+2]*BI[2] + BI[3+i];
        #pragma unroll
        for (int i = 0; i < 3; i++)
            h2[i] = M2[i*3+0]*h1[0] + M2[i*3+1]*h1[1] + M2[i*3+2]*h1[2] + BI[6+i];
        float beta = sm3[0]*h2[0] + sm3[1]*h2[1] + sm3[2]*h2[2] + BI[9];

        bool affine = true;
        #pragma unroll
        for (int j = 0; j < 9; j++) affine = affine && (TF[j] == 0.0f);

        float ep = expm1f(A);      // e^A - 1  (A > 0)
        float em = expm1f(-A);     // e^-A - 1 (negative)
        CC[0] = A;
        CC[1] = fmaf(0.5f, A, beta);   // B1: U = A*x + B1
        CC[2] = ep + 1.0f;             // KP = e^A
        CC[3] = em + 1.0f;             // KM = e^-A
        CC[4] = ep;                    // DP = |e^A - 1|
        CC[5] = -em;                   // DM = |e^-A - 1|
        CC[6] = affine ? 1.0f : 0.0f;
    }
    __syncthreads();

    const int base = slab * (HW / 4);

    if (CC[6] != 0.0f) {
        // ------- collapsed affine fast path -------
        const float A  = CC[0], B1 = CC[1];
        const float KP = CC[2], KM = CC[3], DP = CC[4], DM = CC[5];

        // front-batch the 4 vector loads for MLP
        float4 v[4];
        #pragma unroll
        for (int k = 0; k < 4; k++)
            v[k] = __ldcs(&x4[base + tid + k * 256]);

        #pragma unroll
        for (int k = 0; k < 4; k++) {
            float4 r;
            const float* vp = &v[k].x;
            float* rp = &r.x;
            #pragma unroll
            for (int e = 0; e < 4; e++) {
                const float U    = fmaf(A, vp[e], B1);
                const float sum2 = fmaf(2.0f, U, -A);          // = L + U
                const bool  pos  = (sum2 > 0.0f);
                const float kk   = pos ? KM : KP;              // e^{sA}
                float d          = pos ? DM : DP;              // |e^{sA}-1|
                if (sum2 == 0.0f) d = 0.0f;                    // s==0 edge case
                float arg        = pos ? U : -U;               // t = e^{-sU}
                arg              = fminf(arg, 80.0f);
                const float t    = __expf(arg);
                const float num  = t * d;
                const float den  = (1.0f + t) * fmaf(t, kk, 1.0f);
                const float like = num * __frcp_rn(den);
                rp[e] = fmaxf(like, 1e-6f);
            }
            __stcs(&o4[base + tid + k * 256], r);
        }
        return;
    }

    // ------- generic layered fallback (non-affine factors) -------
    {
        const float b3 = BI[9];
        auto chain = [&](float t) -> float {
            float h[3], g[3];
            #pragma unroll
            for (int j = 0; j < 3; j++) {
                h[j] = fmaf(W[j], t, BI[j]);
                h[j] = fmaf(TF[j], tanhf(h[j]), h[j]);
            }
            #pragma unroll
            for (int i = 0; i < 3; i++) {
                g[i] = fmaf(W[3+i*3+0], h[0], fmaf(W[3+i*3+1], h[1],
                       fmaf(W[3+i*3+2], h[2], BI[3+i])));
                g[i] = fmaf(TF[3+i], tanhf(g[i]), g[i]);
            }
            #pragma unroll
            for (int i = 0; i < 3; i++) {
                h[i] = fmaf(W[12+i*3+0], g[0], fmaf(W[12+i*3+1], g[1],
                       fmaf(W[12+i*3+2], g[2], BI[6+i])));
                h[i] = fmaf(TF[6+i], tanhf(h[i]), h[i]);
            }
            return fmaf(W[21], h[0], fmaf(W[22], h[1], fmaf(W[23], h[2], b3)));
        };

        #pragma unroll
        for (int k = 0; k < 4; k++) {
            const int idx = base + tid + k * 256;
            float4 v = x4[idx];
            float4 r;
            const float* vp = &v.x;
            float* rp = &r.x;
            #pragma unroll
            for (int e = 0; e < 4; e++) {
                const float L = chain(vp[e] - 0.5f);
                const float U = chain(vp[e] + 0.5f);
                const float sum = L + U;
                const float s = (sum > 0.0f) ? -1.0f : ((sum < 0.0f) ? 1.0f : 0.0f);
                const float a  = fminf(s * U, 80.0f);
                const float bb = fminf(s * L, 80.0f);
                const float sa = __fdividef(1.0f, 1.0f + __expf(-a));
                const float sb = __fdividef(1.0f, 1.0f + __expf(-bb));
                rp[e] = fmaxf(fabsf(sa - sb), 1e-6f);
            }
            o4[idx] = r;
        }
    }
}

extern "C" void kernel_launch(void* const* d_in, const int* in_sizes, int n_in,
                              void* d_out, int out_size) {
    const float* x = (const float*)d_in[0];
    const float *m0, *m1, *m2, *m3, *b0, *b1, *b2, *b3, *f0, *f1, *f2;

    // Disambiguate input ordering by element counts:
    //   matrix_1 / matrix_2 are the only 1728-element tensors.
    // setup_inputs dict order: x, m0,b0,f0, m1,b1,f1, m2,b2,f2, m3,b3  -> in_sizes[4]==1728
    // signature order:         x, m0..m3, b0..b3, f0..f2               -> in_sizes[2]==1728
    if (n_in >= 12 && in_sizes[4] == 1728) {
        m0 = (const float*)d_in[1];  b0 = (const float*)d_in[2];  f0 = (const float*)d_in[3];
        m1 = (const float*)d_in[4];  b1 = (const float*)d_in[5];  f1 = (const float*)d_in[6];
        m2 = (const float*)d_in[7];  b2 = (const float*)d_in[8];  f2 = (const float*)d_in[9];
        m3 = (const float*)d_in[10]; b3 = (const float*)d_in[11];
    } else {
        m0 = (const float*)d_in[1];  m1 = (const float*)d_in[2];
        m2 = (const float*)d_in[3];  m3 = (const float*)d_in[4];
        b0 = (const float*)d_in[5];  b1 = (const float*)d_in[6];
        b2 = (const float*)d_in[7];  b3 = (const float*)d_in[8];
        f0 = (const float*)d_in[9];  f1 = (const float*)d_in[10]; f2 = (const float*)d_in[11];
    }

    ent_fused_kernel<<<NSLAB, 256>>>((const float4*)x, (float4*)d_out,
                                     m0, m1, m2, m3, b0, b1, b2, b3, f0, f1, f2);
}

// round 4
// speedup vs baseline: 1.4143x; 1.1059x over previous
#include <cuda_runtime.h>

// Problem constants (fixed by the dataset)
#define C_CH    192
#define HW      4096         // H*W = 64*64 : one block's slab
#define NSLAB   3072         // B*C = 16*192

__device__ __forceinline__ float softplus_acc(float x) {
    return (x > 20.0f) ? x : log1pf(expf(x));   // accurate: weights compound 4 layers
}

__device__ __forceinline__ float ex2_approx(float x) {
    float y;
    asm("ex2.approx.f32 %0, %1;" : "=f"(y) : "f"(x));
    return y;
}

// One fused kernel: per-block prologue derives the channel's collapsed-affine
// constants (or full tables for the generic fallback), then streams the slab.
__global__ __launch_bounds__(256)
void ent_fused_kernel(const float4* __restrict__ x4, float4* __restrict__ o4,
                      const float* __restrict__ m0p, const float* __restrict__ m1p,
                      const float* __restrict__ m2p, const float* __restrict__ m3p,
                      const float* __restrict__ b0p, const float* __restrict__ b1p,
                      const float* __restrict__ b2p, const float* __restrict__ b3p,
                      const float* __restrict__ f0p, const float* __restrict__ f1p,
                      const float* __restrict__ f2p) {
    __shared__ float W[24];    // sm0[0..2], M1[3..11], M2[12..20], sm3[21..23]
    __shared__ float TF[9];    // tanh(factor)
    __shared__ float BI[10];   // b0, b1, b2, b3
    __shared__ float CC[7];    // na, nb, k, d, qa, qb, affine

    const int slab = blockIdx.x;          // = b*C + c
    const int c = slab % C_CH;
    const int tid = threadIdx.x;

    // ---- prologue: distributed transcendentals (accurate softplus/tanh) ----
    if (tid < 24) {
        float v;
        if (tid < 3)       v = m0p[c * 3 + tid];
        else if (tid < 12) v = m1p[c * 9 + (tid - 3)];
        else if (tid < 21) v = m2p[c * 9 + (tid - 12)];
        else               v = m3p[c * 3 + (tid - 21)];
        W[tid] = softplus_acc(v);
    } else if (tid >= 32 && tid < 41) {
        int j = tid - 32;
        float f = (j < 3) ? f0p[c * 3 + j] : (j < 6) ? f1p[c * 3 + (j - 3)]
                                           : f2p[c * 3 + (j - 6)];
        TF[j] = tanhf(f);
    } else if (tid >= 64 && tid < 74) {
        int j = tid - 64;
        BI[j] = (j < 3) ? b0p[c * 3 + j] : (j < 6) ? b1p[c * 3 + (j - 3)]
              : (j < 9) ? b2p[c * 3 + (j - 6)] : b3p[c];
    }
    __syncthreads();

    if (tid == 0) {
        const float* sm0 = W;
        const float* M1  = W + 3;
        const float* M2  = W + 12;
        const float* sm3 = W + 21;
        // slope A = m3 . M2 . M1 . m0
        float d1[3], d2[3];
        #pragma unroll
        for (int i = 0; i < 3; i++)
            d1[i] = M1[i*3+0]*sm0[0] + M1[i*3+1]*sm0[1] + M1[i*3+2]*sm0[2];
        #pragma unroll
        for (int i = 0; i < 3; i++)
            d2[i] = M2[i*3+0]*d1[0] + M2[i*3+1]*d1[1] + M2[i*3+2]*d1[2];
        float A = sm3[0]*d2[0] + sm3[1]*d2[1] + sm3[2]*d2[2];
        // intercept beta = chain(0): biases only
        float h1[3], h2[3];
        #pragma unroll
        for (int i = 0; i < 3; i++)
            h1[i] = M1[i*3+0]*BI[0] + M1[i*3+1]*BI[1] + M1[i*3+2]*BI[2] + BI[3+i];
        #pragma unroll
        for (int i = 0; i < 3; i++)
            h2[i] = M2[i*3+0]*h1[0] + M2[i*3+1]*h1[1] + M2[i*3+2]*h1[2] + BI[6+i];
        float beta = sm3[0]*h2[0] + sm3[1]*h2[1] + sm3[2]*h2[2] + BI[9];

        bool affine = true;
        #pragma unroll
        for (int j = 0; j < 9; j++) affine = affine && (TF[j] == 0.0f);

        // U(x) = A*x + B1,  B1 = beta + A/2
        // like = t*d / ((1+t)(1+t*k)),  t = e^{-U} = 2^(na*x + nb)
        const float LOG2E = 1.4426950408889634f;
        float B1 = fmaf(0.5f, A, beta);
        CC[0] = -A * LOG2E;            // na
        CC[1] = -B1 * LOG2E;           // nb
        CC[2] = expm1f(A) + 1.0f;      // k = e^A
        CC[3] = expm1f(A);             // d = e^A - 1  (> 0)
        CC[4] = 2.0f * A;              // qa : L+U = qa*x + qb  (edge-case guard)
        CC[5] = fmaf(2.0f, beta, A);   // qb = 2*B1 - A
        CC[6] = affine ? 1.0f : 0.0f;
    }
    __syncthreads();

    const int base = slab * (HW / 4);

    if (CC[6] != 0.0f) {
        // ------- collapsed affine fast path: no selects, no cancellation -------
        const float na = CC[0], nb = CC[1], kk = CC[2], dd = CC[3];
        const float qa = CC[4], qb = CC[5];

        float4 v[4];
        #pragma unroll
        for (int k = 0; k < 4; k++)
            v[k] = __ldcs(&x4[base + tid + k * 256]);

        #pragma unroll
        for (int k = 0; k < 4; k++) {
            float4 r;
            const float* vp = &v[k].x;
            float* rp = &r.x;
            #pragma unroll
            for (int e = 0; e < 4; e++) {
                const float x   = vp[e];
                const float arg = fminf(fmaf(na, x, nb), 126.0f);
                const float t   = ex2_approx(arg);            // e^{-U}
                const float q   = fmaf(qa, x, qb);            // L+U (sign guard)
                const float num = t * dd;
                const float den = fmaf(t, kk, 1.0f) * (t + 1.0f);
                float like = __fdividef(num, den);            // rcp.approx + mul
                like = (q == 0.0f) ? 0.0f : like;             // reference s==0 case
                rp[e] = fmaxf(like, 1e-6f);
            }
            __stcs(&o4[base + tid + k * 256], r);
        }
        return;
    }

    // ------- generic layered fallback (non-affine factors) -------
    {
        const float b3 = BI[9];
        auto chain = [&](float t) -> float {
            float h[3], g[3];
            #pragma unroll
            for (int j = 0; j < 3; j++) {
                h[j] = fmaf(W[j], t, BI[j]);
                h[j] = fmaf(TF[j], tanhf(h[j]), h[j]);
            }
            #pragma unroll
            for (int i = 0; i < 3; i++) {
                g[i] = fmaf(W[3+i*3+0], h[0], fmaf(W[3+i*3+1], h[1],
                       fmaf(W[3+i*3+2], h[2], BI[3+i])));
                g[i] = fmaf(TF[3+i], tanhf(g[i]), g[i]);
            }
            #pragma unroll
            for (int i = 0; i < 3; i++) {
                h[i] = fmaf(W[12+i*3+0], g[0], fmaf(W[12+i*3+1], g[1],
                       fmaf(W[12+i*3+2], g[2], BI[6+i])));
                h[i] = fmaf(TF[6+i], tanhf(h[i]), h[i]);
            }
            return fmaf(W[21], h[0], fmaf(W[22], h[1], fmaf(W[23], h[2], b3)));
        };

        #pragma unroll
        for (int k = 0; k < 4; k++) {
            const int idx = base + tid + k * 256;
            float4 v = x4[idx];
            float4 r;
            const float* vp = &v.x;
            float* rp = &r.x;
            #pragma unroll
            for (int e = 0; e < 4; e++) {
                const float L = chain(vp[e] - 0.5f);
                const float U = chain(vp[e] + 0.5f);
                const float sum = L + U;
                const float s = (sum > 0.0f) ? -1.0f : ((sum < 0.0f) ? 1.0f : 0.0f);
                const float a  = fminf(s * U, 80.0f);
                const float bb = fminf(s * L, 80.0f);
                const float sa = __fdividef(1.0f, 1.0f + __expf(-a));
                const float sb = __fdividef(1.0f, 1.0f + __expf(-bb));
                rp[e] = fmaxf(fabsf(sa - sb), 1e-6f);
            }
            o4[idx] = r;
        }
    }
}

extern "C" void kernel_launch(void* const* d_in, const int* in_sizes, int n_in,
                              void* d_out, int out_size) {
    const float* x = (const float*)d_in[0];
    const float *m0, *m1, *m2, *m3, *b0, *b1, *b2, *b3, *f0, *f1, *f2;

    // Disambiguate input ordering by element counts:
    //   matrix_1 / matrix_2 are the only 1728-element tensors.
    if (n_in >= 12 && in_sizes[4] == 1728) {
        m0 = (const float*)d_in[1];  b0 = (const float*)d_in[2];  f0 = (const float*)d_in[3];
        m1 = (const float*)d_in[4];  b1 = (const float*)d_in[5];  f1 = (const float*)d_in[6];
        m2 = (const float*)d_in[7];  b2 = (const float*)d_in[8];  f2 = (const float*)d_in[9];
        m3 = (const float*)d_in[10]; b3 = (const float*)d_in[11];
    } else {
        m0 = (const float*)d_in[1];  m1 = (const float*)d_in[2];
        m2 = (const float*)d_in[3];  m3 = (const float*)d_in[4];
        b0 = (const float*)d_in[5];  b1 = (const float*)d_in[6];
        b2 = (const float*)d_in[7];  b3 = (const float*)d_in[8];
        f0 = (const float*)d_in[9];  f1 = (const float*)d_in[10]; f2 = (const float*)d_in[11];
    }

    ent_fused_kernel<<<NSLAB, 256>>>((const float4*)x, (float4*)d_out,
                                     m0, m1, m2, m3, b0, b1, b2, b3, f0, f1, f2);
}

// round 7
// speedup vs baseline: 1.4277x; 1.0094x over previous
#include <cuda_runtime.h>

// Problem constants (fixed by the dataset)
#define C_CH    192
#define HW4     1024         // float4s per (b,c) slab (64*64/4)
#define NB      2            // slabs (batches) per block
#define GRID_Y  8            // 16 batches / NB

__device__ __forceinline__ float softplus_acc(float x) {
    return (x > 20.0f) ? x : log1pf(expf(x));   // accurate: weights compound 4 layers
}

__device__ __forceinline__ float ex2_approx(float x) {
    float y;
    asm("ex2.approx.f32 %0, %1;" : "=f"(y) : "f"(x));
    return y;
}

// Fused kernel, grid (C_CH, GRID_Y): block (c, y) derives channel-c constants
// once, then streams slabs for batches {NB*y .. NB*y+NB-1}.
__global__ __launch_bounds__(256)
void ent_fused_kernel(const float4* __restrict__ x4, float4* __restrict__ o4,
                      const float* __restrict__ m0p, const float* __restrict__ m1p,
                      const float* __restrict__ m2p, const float* __restrict__ m3p,
                      const float* __restrict__ b0p, const float* __restrict__ b1p,
                      const float* __restrict__ b2p, const float* __restrict__ b3p,
                      const float* __restrict__ f0p, const float* __restrict__ f1p,
                      const float* __restrict__ f2p) {
    __shared__ float W[24];    // sm0[0..2], M1[3..11], M2[12..20], sm3[21..23]
    __shared__ float TF[9];    // tanh(factor)
    __shared__ float BI[10];   // b0, b1, b2, b3
    __shared__ float CC[7];    // na, nb, k, d, qa, qb, affine

    const int c   = blockIdx.x;
    const int tid = threadIdx.x;

    // ---- prologue: distributed transcendentals (accurate softplus/tanh) ----
    if (tid < 24) {
        float v;
        if (tid < 3)       v = m0p[c * 3 + tid];
        else if (tid < 12) v = m1p[c * 9 + (tid - 3)];
        else if (tid < 21) v = m2p[c * 9 + (tid - 12)];
        else               v = m3p[c * 3 + (tid - 21)];
        W[tid] = softplus_acc(v);
    } else if (tid >= 32 && tid < 41) {
        int j = tid - 32;
        float f = (j < 3) ? f0p[c * 3 + j] : (j < 6) ? f1p[c * 3 + (j - 3)]
                                           : f2p[c * 3 + (j - 6)];
        TF[j] = tanhf(f);
    } else if (tid >= 64 && tid < 74) {
        int j = tid - 64;
        BI[j] = (j < 3) ? b0p[c * 3 + j] : (j < 6) ? b1p[c * 3 + (j - 3)]
              : (j < 9) ? b2p[c * 3 + (j - 6)] : b3p[c];
    }
    __syncthreads();

    if (tid == 0) {
        const float* sm0 = W;
        const float* M1  = W + 3;
        const float* M2  = W + 12;
        const float* sm3 = W + 21;
        // slope A = m3 . M2 . M1 . m0
        float d1[3], d2[3];
        #pragma unroll
        for (int i = 0; i < 3; i++)
            d1[i] = M1[i*3+0]*sm0[0] + M1[i*3+1]*sm0[1] + M1[i*3+2]*sm0[2];
        #pragma unroll
        for (int i = 0; i < 3; i++)
            d2[i] = M2[i*3+0]*d1[0] + M2[i*3+1]*d1[1] + M2[i*3+2]*d1[2];
        float A = sm3[0]*d2[0] + sm3[1]*d2[1] + sm3[2]*d2[2];
        // intercept beta = chain(0): biases only
        float h1[3], h2[3];
        #pragma unroll
        for (int i = 0; i < 3; i++)
            h1[i] = M1[i*3+0]*BI[0] + M1[i*3+1]*BI[1] + M1[i*3+2]*BI[2] + BI[3+i];
        #pragma unroll
        for (int i = 0; i < 3; i++)
            h2[i] = M2[i*3+0]*h1[0] + M2[i*3+1]*h1[1] + M2[i*3+2]*h1[2] + BI[6+i];
        float beta = sm3[0]*h2[0] + sm3[1]*h2[1] + sm3[2]*h2[2] + BI[9];

        bool affine = true;
        #pragma unroll
        for (int j = 0; j < 9; j++) affine = affine && (TF[j] == 0.0f);

        // U(x) = A*x + B1,  B1 = beta + A/2
        // like = t*d / ((1+t)(1+t*k)),  t = e^{-U} = 2^(na*x + nb)
        const float LOG2E = 1.4426950408889634f;
        float B1 = fmaf(0.5f, A, beta);
        CC[0] = -A * LOG2E;            // na
        CC[1] = -B1 * LOG2E;           // nb
        CC[2] = expm1f(A) + 1.0f;      // k = e^A
        CC[3] = expm1f(A);             // d = e^A - 1  (> 0)
        CC[4] = 2.0f * A;              // qa : L+U = qa*x + qb  (edge-case guard)
        CC[5] = fmaf(2.0f, beta, A);   // qb
        CC[6] = affine ? 1.0f : 0.0f;
    }
    __syncthreads();

    // slab indices for this block: batches NB*y .. NB*y+NB-1, channel c
    int base[NB];
    #pragma unroll
    for (int s = 0; s < NB; s++)
        base[s] = ((NB * blockIdx.y + s) * C_CH + c) * HW4;

    if (CC[6] != 0.0f) {
        // ------- collapsed affine fast path: no selects, no cancellation -------
        const float na = CC[0], nb = CC[1], kk = CC[2], dd = CC[3];
        const float qa = CC[4], qb = CC[5];

        // front-batch all NB*4 vector loads (MLP = 8)
        float4 v[NB][4];
        #pragma unroll
        for (int s = 0; s < NB; s++)
            #pragma unroll
            for (int k = 0; k < 4; k++)
                v[s][k] = __ldcs(&x4[base[s] + tid + k * 256]);

        #pragma unroll
        for (int s = 0; s < NB; s++) {
            #pragma unroll
            for (int k = 0; k < 4; k++) {
                float4 r;
                const float* vp = &v[s][k].x;
                float* rp = &r.x;
                #pragma unroll
                for (int e = 0; e < 4; e++) {
                    const float x   = vp[e];
                    const float arg = fminf(fmaf(na, x, nb), 126.0f);
                    const float t   = ex2_approx(arg);            // e^{-U}
                    const float q   = fmaf(qa, x, qb);            // L+U (sign guard)
                    const float num = t * dd;
                    const float den = fmaf(t, kk, 1.0f) * (t + 1.0f);
                    float like = __fdividef(num, den);
                    like = (q == 0.0f) ? 0.0f : like;             // reference s==0 case
                    rp[e] = fmaxf(like, 1e-6f);
                }
                __stcs(&o4[base[s] + tid + k * 256], r);
            }
        }
        return;
    }

    // ------- generic layered fallback (non-affine factors) -------
    {
        const float b3 = BI[9];
        auto chain = [&](float t) -> float {
            float h[3], g[3];
            #pragma unroll
            for (int j = 0; j < 3; j++) {
                h[j] = fmaf(W[j], t, BI[j]);
                h[j] = fmaf(TF[j], tanhf(h[j]), h[j]);
            }
            #pragma unroll
            for (int i = 0; i < 3; i++) {
                g[i] = fmaf(W[3+i*3+0], h[0], fmaf(W[3+i*3+1], h[1],
                       fmaf(W[3+i*3+2], h[2], BI[3+i])));
                g[i] = fmaf(TF[3+i], tanhf(g[i]), g[i]);
            }
            #pragma unroll
            for (int i = 0; i < 3; i++) {
                h[i] = fmaf(W[12+i*3+0], g[0], fmaf(W[12+i*3+1], g[1],
                       fmaf(W[12+i*3+2], g[2], BI[6+i])));
                h[i] = fmaf(TF[6+i], tanhf(h[i]), h[i]);
            }
            return fmaf(W[21], h[0], fmaf(W[22], h[1], fmaf(W[23], h[2], b3)));
        };

        for (int s = 0; s < NB; s++) {
            #pragma unroll
            for (int k = 0; k < 4; k++) {
                const int idx = base[s] + tid + k * 256;
                float4 v = x4[idx];
                float4 r;
                const float* vp = &v.x;
                float* rp = &r.x;
                #pragma unroll
                for (int e = 0; e < 4; e++) {
                    const float L = chain(vp[e] - 0.5f);
                    const float U = chain(vp[e] + 0.5f);
                    const float sum = L + U;
                    const float sgn = (sum > 0.0f) ? -1.0f : ((sum < 0.0f) ? 1.0f : 0.0f);
                    const float a  = fminf(sgn * U, 80.0f);
                    const float bb = fminf(sgn * L, 80.0f);
                    const float sa = __fdividef(1.0f, 1.0f + __expf(-a));
                    const float sb = __fdividef(1.0f, 1.0f + __expf(-bb));
                    rp[e] = fmaxf(fabsf(sa - sb), 1e-6f);
                }
                o4[idx] = r;
            }
        }
    }
}

extern "C" void kernel_launch(void* const* d_in, const int* in_sizes, int n_in,
                              void* d_out, int out_size) {
    const float* x = (const float*)d_in[0];
    const float *m0, *m1, *m2, *m3, *b0, *b1, *b2, *b3, *f0, *f1, *f2;

    // Disambiguate input ordering by element counts:
    //   matrix_1 / matrix_2 are the only 1728-element tensors.
    if (n_in >= 12 && in_sizes[4] == 1728) {
        m0 = (const float*)d_in[1];  b0 = (const float*)d_in[2];  f0 = (const float*)d_in[3];
        m1 = (const float*)d_in[4];  b1 = (const float*)d_in[5];  f1 = (const float*)d_in[6];
        m2 = (const float*)d_in[7];  b2 = (const float*)d_in[8];  f2 = (const float*)d_in[9];
        m3 = (const float*)d_in[10]; b3 = (const float*)d_in[11];
    } else {
        m0 = (const float*)d_in[1];  m1 = (const float*)d_in[2];
        m2 = (const float*)d_in[3];  m3 = (const float*)d_in[4];
        b0 = (const float*)d_in[5];  b1 = (const float*)d_in[6];
        b2 = (const float*)d_in[7];  b3 = (const float*)d_in[8];
        f0 = (const float*)d_in[9];  f1 = (const float*)d_in[10]; f2 = (const float*)d_in[11];
    }

    dim3 grid(C_CH, GRID_Y);
    ent_fused_kernel<<<grid, 256>>>((const float4*)x, (float4*)d_out,
                                    m0, m1, m2, m3, b0, b1, b2, b3, f0, f1, f2);
}

// round 9
// speedup vs baseline: 1.5764x; 1.1042x over previous
#include <cuda_runtime.h>

// Problem constants (fixed by the dataset)
#define C_CH    192
#define HW4     1024         // float4s per (b,c) slab (64*64/4)
#define NB      2            // slabs (batches) per block
#define GRID_Y  8            // 16 batches / NB

__device__ __forceinline__ float softplus_acc(float x) {
    return (x > 20.0f) ? x : log1pf(expf(x));   // accurate: weights compound 4 layers
}

__device__ __forceinline__ float ex2_approx(float x) {
    float y;
    asm("ex2.approx.f32 %0, %1;" : "=f"(y) : "f"(x));
    return y;
}

// Fused kernel, grid (C_CH, GRID_Y): block (c, y) derives channel-c constants
// once, then streams slabs for batches {NB*y .. NB*y+NB-1}.
__global__ __launch_bounds__(256)
void ent_fused_kernel(const float4* __restrict__ x4, float4* __restrict__ o4,
                      const float* __restrict__ m0p, const float* __restrict__ m1p,
                      const float* __restrict__ m2p, const float* __restrict__ m3p,
                      const float* __restrict__ b0p, const float* __restrict__ b1p,
                      const float* __restrict__ b2p, const float* __restrict__ b3p,
                      const float* __restrict__ f0p, const float* __restrict__ f1p,
                      const float* __restrict__ f2p) {
    __shared__ float W[24];    // sm0[0..2], M1[3..11], M2[12..20], sm3[21..23]
    __shared__ float TF[9];    // tanh(factor)
    __shared__ float BI[10];   // b0, b1, b2, b3
    __shared__ float CC[7];    // na, nb, k, d, qa, qb, affine

    const int c   = blockIdx.x;
    const int tid = threadIdx.x;

    // ---- prologue: distributed transcendentals (accurate softplus/tanh) ----
    if (tid < 24) {
        float v;
        if (tid < 3)       v = m0p[c * 3 + tid];
        else if (tid < 12) v = m1p[c * 9 + (tid - 3)];
        else if (tid < 21) v = m2p[c * 9 + (tid - 12)];
        else               v = m3p[c * 3 + (tid - 21)];
        W[tid] = softplus_acc(v);
    } else if (tid >= 32 && tid < 41) {
        int j = tid - 32;
        float f = (j < 3) ? f0p[c * 3 + j] : (j < 6) ? f1p[c * 3 + (j - 3)]
                                           : f2p[c * 3 + (j - 6)];
        TF[j] = tanhf(f);
    } else if (tid >= 64 && tid < 74) {
        int j = tid - 64;
        BI[j] = (j < 3) ? b0p[c * 3 + j] : (j < 6) ? b1p[c * 3 + (j - 3)]
              : (j < 9) ? b2p[c * 3 + (j - 6)] : b3p[c];
    }
    __syncthreads();

    if (tid == 0) {
        const float* sm0 = W;
        const float* M1  = W + 3;
        const float* M2  = W + 12;
        const float* sm3 = W + 21;
        // slope A = m3 . M2 . M1 . m0
        float d1[3], d2[3];
        #pragma unroll
        for (int i = 0; i < 3; i++)
            d1[i] = M1[i*3+0]*sm0[0] + M1[i*3+1]*sm0[1] + M1[i*3+2]*sm0[2];
        #pragma unroll
        for (int i = 0; i < 3; i++)
            d2[i] = M2[i*3+0]*d1[0] + M2[i*3+1]*d1[1] + M2[i*3+2]*d1[2];
        float A = sm3[0]*d2[0] + sm3[1]*d2[1] + sm3[2]*d2[2];
        // intercept beta = chain(0): biases only
        float h1[3], h2[3];
        #pragma unroll
        for (int i = 0; i < 3; i++)
            h1[i] = M1[i*3+0]*BI[0] + M1[i*3+1]*BI[1] + M1[i*3+2]*BI[2] + BI[3+i];
        #pragma unroll
        for (int i = 0; i < 3; i++)
            h2[i] = M2[i*3+0]*h1[0] + M2[i*3+1]*h1[1] + M2[i*3+2]*h1[2] + BI[6+i];
        float beta = sm3[0]*h2[0] + sm3[1]*h2[1] + sm3[2]*h2[2] + BI[9];

        bool affine = true;
        #pragma unroll
        for (int j = 0; j < 9; j++) affine = affine && (TF[j] == 0.0f);

        // U(x) = A*x + B1,  B1 = beta + A/2
        // like = t*d / ((1+t)(1+t*k)),  t = e^{-U} = 2^(na*x + nb)
        const float LOG2E = 1.4426950408889634f;
        float B1 = fmaf(0.5f, A, beta);
        CC[0] = -A * LOG2E;            // na
        CC[1] = -B1 * LOG2E;           // nb
        CC[2] = expm1f(A) + 1.0f;      // k = e^A
        CC[3] = expm1f(A);             // d = e^A - 1  (> 0)
        CC[4] = 2.0f * A;              // qa : L+U = qa*x + qb  (edge-case guard)
        CC[5] = fmaf(2.0f, beta, A);   // qb
        CC[6] = affine ? 1.0f : 0.0f;
    }
    __syncthreads();

    // slab indices for this block: batches NB*y .. NB*y+NB-1, channel c
    int base[NB];
    #pragma unroll
    for (int s = 0; s < NB; s++)
        base[s] = ((NB * blockIdx.y + s) * C_CH + c) * HW4;

    if (CC[6] != 0.0f) {
        // ------- collapsed affine fast path: no selects, no cancellation -------
        const float na = CC[0], nb = CC[1], kk = CC[2], dd = CC[3];
        const float qa = CC[4], qb = CC[5];

        // two-phase: per slab, batch 4 loads (MLP=4) then compute — keeps
        // register pressure down for higher occupancy; default caching keeps
        // the working set L2-resident across graph replays.
        #pragma unroll
        for (int s = 0; s < NB; s++) {
            float4 v[4];
            #pragma unroll
            for (int k = 0; k < 4; k++)
                v[k] = x4[base[s] + tid + k * 256];

            #pragma unroll
            for (int k = 0; k < 4; k++) {
                float4 r;
                const float* vp = &v[k].x;
                float* rp = &r.x;
                #pragma unroll
                for (int e = 0; e < 4; e++) {
                    const float x   = vp[e];
                    const float arg = fminf(fmaf(na, x, nb), 126.0f);
                    const float t   = ex2_approx(arg);            // e^{-U}
                    const float q   = fmaf(qa, x, qb);            // L+U (sign guard)
                    const float num = t * dd;
                    const float den = fmaf(t, kk, 1.0f) * (t + 1.0f);
                    float like = __fdividef(num, den);
                    like = (q == 0.0f) ? 0.0f : like;             // reference s==0 case
                    rp[e] = fmaxf(like, 1e-6f);
                }
                o4[base[s] + tid + k * 256] = r;
            }
        }
        return;
    }

    // ------- generic layered fallback (non-affine factors) -------
    {
        const float b3 = BI[9];
        auto chain = [&](float t) -> float {
            float h[3], g[3];
            #pragma unroll
            for (int j = 0; j < 3; j++) {
                h[j] = fmaf(W[j], t, BI[j]);
                h[j] = fmaf(TF[j], tanhf(h[j]), h[j]);
            }
            #pragma unroll
            for (int i = 0; i < 3; i++) {
                g[i] = fmaf(W[3+i*3+0], h[0], fmaf(W[3+i*3+1], h[1],
                       fmaf(W[3+i*3+2], h[2], BI[3+i])));
                g[i] = fmaf(TF[3+i], tanhf(g[i]), g[i]);
            }
            #pragma unroll
            for (int i = 0; i < 3; i++) {
                h[i] = fmaf(W[12+i*3+0], g[0], fmaf(W[12+i*3+1], g[1],
                       fmaf(W[12+i*3+2], g[2], BI[6+i])));
                h[i] = fmaf(TF[6+i], tanhf(h[i]), h[i]);
            }
            return fmaf(W[21], h[0], fmaf(W[22], h[1], fmaf(W[23], h[2], b3)));
        };

        for (int s = 0; s < NB; s++) {
            #pragma unroll
            for (int k = 0; k < 4; k++) {
                const int idx = base[s] + tid + k * 256;
                float4 v = x4[idx];
                float4 r;
                const float* vp = &v.x;
                float* rp = &r.x;
                #pragma unroll
                for (int e = 0; e < 4; e++) {
                    const float L = chain(vp[e] - 0.5f);
                    const float U = chain(vp[e] + 0.5f);
                    const float sum = L + U;
                    const float sgn = (sum > 0.0f) ? -1.0f : ((sum < 0.0f) ? 1.0f : 0.0f);
                    const float a  = fminf(sgn * U, 80.0f);
                    const float bb = fminf(sgn * L, 80.0f);
                    const float sa = __fdividef(1.0f, 1.0f + __expf(-a));
                    const float sb = __fdividef(1.0f, 1.0f + __expf(-bb));
                    rp[e] = fmaxf(fabsf(sa - sb), 1e-6f);
                }
                o4[idx] = r;
            }
        }
    }
}

extern "C" void kernel_launch(void* const* d_in, const int* in_sizes, int n_in,
                              void* d_out, int out_size) {
    const float* x = (const float*)d_in[0];
    const float *m0, *m1, *m2, *m3, *b0, *b1, *b2, *b3, *f0, *f1, *f2;

    // Disambiguate input ordering by element counts:
    //   matrix_1 / matrix_2 are the only 1728-element tensors.
    if (n_in >= 12 && in_sizes[4] == 1728) {
        m0 = (const float*)d_in[1];  b0 = (const float*)d_in[2];  f0 = (const float*)d_in[3];
        m1 = (const float*)d_in[4];  b1 = (const float*)d_in[5];  f1 = (const float*)d_in[6];
        m2 = (const float*)d_in[7];  b2 = (const float*)d_in[8];  f2 = (const float*)d_in[9];
        m3 = (const float*)d_in[10]; b3 = (const float*)d_in[11];
    } else {
        m0 = (const float*)d_in[1];  m1 = (const float*)d_in[2];
        m2 = (const float*)d_in[3];  m3 = (const float*)d_in[4];
        b0 = (const float*)d_in[5];  b1 = (const float*)d_in[6];
        b2 = (const float*)d_in[7];  b3 = (const float*)d_in[8];
        f0 = (const float*)d_in[9];  f1 = (const float*)d_in[10]; f2 = (const float*)d_in[11];
    }

    dim3 grid(C_CH, GRID_Y);
    ent_fused_kernel<<<grid, 256>>>((const float4*)x, (float4*)d_out,
                                    m0, m1, m2, m3, b0, b1, b2, b3, f0, f1, f2);
}

// round 10
// speedup vs baseline: 1.7428x; 1.1056x over previous
#include <cuda_runtime.h>

// Problem constants (fixed by the dataset)
#define C_CH    192
#define HW4     1024         // float4s per (b,c) slab (64*64/4)
#define NB      4            // slabs (batches) per block
#define GRID_Y  4            // 16 batches / NB  -> grid 192*4 = 768 blocks
                             // regs~37 -> 6 blocks/SM -> 888 concurrent: ONE wave

__device__ __forceinline__ float softplus_acc(float x) {
    return (x > 20.0f) ? x : log1pf(expf(x));   // accurate: weights compound 4 layers
}

__device__ __forceinline__ float ex2_approx(float x) {
    float y;
    asm("ex2.approx.f32 %0, %1;" : "=f"(y) : "f"(x));
    return y;
}

// Fused kernel, grid (C_CH, GRID_Y): block (c, y) derives channel-c constants
// once, then streams slabs for batches {NB*y .. NB*y+NB-1}.
__global__ __launch_bounds__(256)
void ent_fused_kernel(const float4* __restrict__ x4, float4* __restrict__ o4,
                      const float* __restrict__ m0p, const float* __restrict__ m1p,
                      const float* __restrict__ m2p, const float* __restrict__ m3p,
                      const float* __restrict__ b0p, const float* __restrict__ b1p,
                      const float* __restrict__ b2p, const float* __restrict__ b3p,
                      const float* __restrict__ f0p, const float* __restrict__ f1p,
                      const float* __restrict__ f2p) {
    __shared__ float W[24];    // sm0[0..2], M1[3..11], M2[12..20], sm3[21..23]
    __shared__ float TF[9];    // tanh(factor)
    __shared__ float BI[10];   // b0, b1, b2, b3
    __shared__ float CC[7];    // na, nb, k, d, qa, qb, affine

    const int c   = blockIdx.x;
    const int tid = threadIdx.x;

    // ---- prologue: distributed transcendentals (accurate softplus/tanh) ----
    if (tid < 24) {
        float v;
        if (tid < 3)       v = m0p[c * 3 + tid];
        else if (tid < 12) v = m1p[c * 9 + (tid - 3)];
        else if (tid < 21) v = m2p[c * 9 + (tid - 12)];
        else               v = m3p[c * 3 + (tid - 21)];
        W[tid] = softplus_acc(v);
    } else if (tid >= 32 && tid < 41) {
        int j = tid - 32;
        float f = (j < 3) ? f0p[c * 3 + j] : (j < 6) ? f1p[c * 3 + (j - 3)]
                                           : f2p[c * 3 + (j - 6)];
        TF[j] = tanhf(f);
    } else if (tid >= 64 && tid < 74) {
        int j = tid - 64;
        BI[j] = (j < 3) ? b0p[c * 3 + j] : (j < 6) ? b1p[c * 3 + (j - 3)]
              : (j < 9) ? b2p[c * 3 + (j - 6)] : b3p[c];
    }
    __syncthreads();

    if (tid == 0) {
        const float* sm0 = W;
        const float* M1  = W + 3;
        const float* M2  = W + 12;
        const float* sm3 = W + 21;
        // slope A = m3 . M2 . M1 . m0
        float d1[3], d2[3];
        #pragma unroll
        for (int i = 0; i < 3; i++)
            d1[i] = M1[i*3+0]*sm0[0] + M1[i*3+1]*sm0[1] + M1[i*3+2]*sm0[2];
        #pragma unroll
        for (int i = 0; i < 3; i++)
            d2[i] = M2[i*3+0]*d1[0] + M2[i*3+1]*d1[1] + M2[i*3+2]*d1[2];
        float A = sm3[0]*d2[0] + sm3[1]*d2[1] + sm3[2]*d2[2];
        // intercept beta = chain(0): biases only
        float h1[3], h2[3];
        #pragma unroll
        for (int i = 0; i < 3; i++)
            h1[i] = M1[i*3+0]*BI[0] + M1[i*3+1]*BI[1] + M1[i*3+2]*BI[2] + BI[3+i];
        #pragma unroll
        for (int i = 0; i < 3; i++)
            h2[i] = M2[i*3+0]*h1[0] + M2[i*3+1]*h1[1] + M2[i*3+2]*h1[2] + BI[6+i];
        float beta = sm3[0]*h2[0] + sm3[1]*h2[1] + sm3[2]*h2[2] + BI[9];

        bool affine = true;
        #pragma unroll
        for (int j = 0; j < 9; j++) affine = affine && (TF[j] == 0.0f);

        // U(x) = A*x + B1,  B1 = beta + A/2
        // like = t*d / ((1+t)(1+t*k)),  t = e^{-U} = 2^(na*x + nb)
        const float LOG2E = 1.4426950408889634f;
        float B1 = fmaf(0.5f, A, beta);
        CC[0] = -A * LOG2E;            // na
        CC[1] = -B1 * LOG2E;           // nb
        CC[2] = expm1f(A) + 1.0f;      // k = e^A
        CC[3] = expm1f(A);             // d = e^A - 1  (> 0)
        CC[4] = 2.0f * A;              // qa : L+U = qa*x + qb  (edge-case guard)
        CC[5] = fmaf(2.0f, beta, A);   // qb
        CC[6] = affine ? 1.0f : 0.0f;
    }
    __syncthreads();

    if (CC[6] != 0.0f) {
        // ------- collapsed affine fast path: no selects, no cancellation -------
        const float na = CC[0], nb = CC[1], kk = CC[2], dd = CC[3];
        const float qa = CC[4], qb = CC[5];

        // two-phase per slab: batch 4 loads (MLP=4) then compute — keeps
        // register pressure low (6 blocks/SM); default caching keeps the
        // working set L2-resident across graph replays.
        #pragma unroll
        for (int s = 0; s < NB; s++) {
            const int base = ((NB * blockIdx.y + s) * C_CH + c) * HW4;
            float4 v[4];
            #pragma unroll
            for (int k = 0; k < 4; k++)
                v[k] = x4[base + tid + k * 256];

            #pragma unroll
            for (int k = 0; k < 4; k++) {
                float4 r;
                const float* vp = &v[k].x;
                float* rp = &r.x;
                #pragma unroll
                for (int e = 0; e < 4; e++) {
                    const float x   = vp[e];
                    const float arg = fminf(fmaf(na, x, nb), 126.0f);
                    const float t   = ex2_approx(arg);            // e^{-U}
                    const float q   = fmaf(qa, x, qb);            // L+U (sign guard)
                    const float num = t * dd;
                    const float den = fmaf(t, kk, 1.0f) * (t + 1.0f);
                    float like = __fdividef(num, den);
                    like = (q == 0.0f) ? 0.0f : like;             // reference s==0 case
                    rp[e] = fmaxf(like, 1e-6f);
                }
                o4[base + tid + k * 256] = r;
            }
        }
        return;
    }

    // ------- generic layered fallback (non-affine factors) -------
    {
        const float b3 = BI[9];
        auto chain = [&](float t) -> float {
            float h[3], g[3];
            #pragma unroll
            for (int j = 0; j < 3; j++) {
                h[j] = fmaf(W[j], t, BI[j]);
                h[j] = fmaf(TF[j], tanhf(h[j]), h[j]);
            }
            #pragma unroll
            for (int i = 0; i < 3; i++) {
                g[i] = fmaf(W[3+i*3+0], h[0], fmaf(W[3+i*3+1], h[1],
                       fmaf(W[3+i*3+2], h[2], BI[3+i])));
                g[i] = fmaf(TF[3+i], tanhf(g[i]), g[i]);
            }
            #pragma unroll
            for (int i = 0; i < 3; i++) {
                h[i] = fmaf(W[12+i*3+0], g[0], fmaf(W[12+i*3+1], g[1],
                       fmaf(W[12+i*3+2], g[2], BI[6+i])));
                h[i] = fmaf(TF[6+i], tanhf(h[i]), h[i]);
            }
            return fmaf(W[21], h[0], fmaf(W[22], h[1], fmaf(W[23], h[2], b3)));
        };

        for (int s = 0; s < NB; s++) {
            const int base = ((NB * blockIdx.y + s) * C_CH + c) * HW4;
            #pragma unroll
            for (int k = 0; k < 4; k++) {
                const int idx = base + tid + k * 256;
                float4 v = x4[idx];
                float4 r;
                const float* vp = &v.x;
                float* rp = &r.x;
                #pragma unroll
                for (int e = 0; e < 4; e++) {
                    const float L = chain(vp[e] - 0.5f);
                    const float U = chain(vp[e] + 0.5f);
                    const float sum = L + U;
                    const float sgn = (sum > 0.0f) ? -1.0f : ((sum < 0.0f) ? 1.0f : 0.0f);
                    const float a  = fminf(sgn * U, 80.0f);
                    const float bb = fminf(sgn * L, 80.0f);
                    const float sa = __fdividef(1.0f, 1.0f + __expf(-a));
                    const float sb = __fdividef(1.0f, 1.0f + __expf(-bb));
                    rp[e] = fmaxf(fabsf(sa - sb), 1e-6f);
                }
                o4[idx] = r;
            }
        }
    }
}

extern "C" void kernel_launch(void* const* d_in, const int* in_sizes, int n_in,
                              void* d_out, int out_size) {
    const float* x = (const float*)d_in[0];
    const float *m0, *m1, *m2, *m3, *b0, *b1, *b2, *b3, *f0, *f1, *f2;

    // Disambiguate input ordering by element counts:
    //   matrix_1 / matrix_2 are the only 1728-element tensors.
    if (n_in >= 12 && in_sizes[4] == 1728) {
        m0 = (const float*)d_in[1];  b0 = (const float*)d_in[2];  f0 = (const float*)d_in[3];
        m1 = (const float*)d_in[4];  b1 = (const float*)d_in[5];  f1 = (const float*)d_in[6];
        m2 = (const float*)d_in[7];  b2 = (const float*)d_in[8];  f2 = (const float*)d_in[9];
        m3 = (const float*)d_in[10]; b3 = (const float*)d_in[11];
    } else {
        m0 = (const float*)d_in[1];  m1 = (const float*)d_in[2];
        m2 = (const float*)d_in[3];  m3 = (const float*)d_in[4];
        b0 = (const float*)d_in[5];  b1 = (const float*)d_in[6];
        b2 = (const float*)d_in[7];  b3 = (const float*)d_in[8];
        f0 = (const float*)d_in[9];  f1 = (const float*)d_in[10]; f2 = (const float*)d_in[11];
    }

    dim3 grid(C_CH, GRID_Y);
    ent_fused_kernel<<<grid, 256>>>((const float4*)x, (float4*)d_out,
                                    m0, m1, m2, m3, b0, b1, b2, b3, f0, f1, f2);
}